// round 13
// baseline (speedup 1.0000x reference)
#include <cuda_runtime.h>
#include <cuda_bf16.h>
#include <cuda_fp16.h>
#include <math.h>
#include <stdint.h>

#define B_    4
#define N_    4096
#define DIN_  512
#define DOUT_ 128
#define MAXDEG 128
#define NEG_BIG -1e30f

// ---------------- scratch (static device memory; no allocs) ----------------
__device__ __half g_whh[B_ * N_ * DOUT_];   // x @ W (fp16)   4 MB
__device__ __half g_outh[B_ * N_ * DOUT_];  // att @ wh       4 MB
__device__ float g_sT[N_ * 4];              // s transposed [i][b]
__device__ float g_dT[N_ * 4];              // d transposed [i][b]
__device__ float g_sumwh[B_ * DOUT_];       // per-graph colsum (deg==0 fallback)
__device__ int   g_cols[N_ * MAXDEG];
__device__ int   g_deg[N_];
__device__ uint32_t g_Wh[DIN_ * DOUT_ / 2]; // W as fp16x2 packed (128 KB)

// ============================ helpers =======================================
__device__ __forceinline__ uint32_t smem_u32(const void* p) {
    uint32_t a;
    asm("{ .reg .u64 t; cvta.to.shared.u64 t, %1; cvt.u32.u64 %0, t; }" : "=r"(a) : "l"(p));
    return a;
}
__device__ __forceinline__ void ldm_x4(uint32_t* f, uint32_t addr) {
    asm volatile("ldmatrix.sync.aligned.m8n8.x4.shared.b16 {%0,%1,%2,%3}, [%4];"
                 : "=r"(f[0]), "=r"(f[1]), "=r"(f[2]), "=r"(f[3]) : "r"(addr));
}
__device__ __forceinline__ void ldm_x4t(uint32_t* f, uint32_t addr) {
    asm volatile("ldmatrix.sync.aligned.m8n8.x4.trans.shared.b16 {%0,%1,%2,%3}, [%4];"
                 : "=r"(f[0]), "=r"(f[1]), "=r"(f[2]), "=r"(f[3]) : "r"(addr));
}
__device__ __forceinline__ void mma_f16(float* c, const uint32_t* a, const uint32_t* b) {
    asm volatile(
        "mma.sync.aligned.m16n8k16.row.col.f32.f16.f16.f32 "
        "{%0,%1,%2,%3}, {%4,%5,%6,%7}, {%8,%9}, {%0,%1,%2,%3};"
        : "+f"(c[0]), "+f"(c[1]), "+f"(c[2]), "+f"(c[3])
        : "r"(a[0]), "r"(a[1]), "r"(a[2]), "r"(a[3]), "r"(b[0]), "r"(b[1]));
}
__device__ __forceinline__ uint32_t pack_half(float x, float y) {
    __half2 h = __floats2half2_rn(x, y);
    return *(uint32_t*)&h;
}

// =============== W -> fp16 + zero g_sumwh ==================================
__global__ __launch_bounds__(256) void convw_kernel(const float* __restrict__ W) {
    if (blockIdx.x < 2) g_sumwh[blockIdx.x * 256 + threadIdx.x] = 0.0f;
    int i = blockIdx.x * 256 + threadIdx.x;     // 16384 float4s
    float4 v = ((const float4*)W)[i];
    g_Wh[i * 2]     = pack_half(v.x, v.y);
    g_Wh[i * 2 + 1] = pack_half(v.z, v.w);
}

// =============== CSR build: warp/row, 4 loads in flight ====================
__global__ void csr_build_kernel(const float* __restrict__ adj) {
    int warp = (blockIdx.x * blockDim.x + threadIdx.x) >> 5;
    int lane = threadIdx.x & 31;
    if (warp >= N_) return;
    const float4* row = (const float4*)(adj + (size_t)warp * N_);
    int cnt = 0;
    for (int base = 0; base < N_; base += 512) {
        float4 v0 = row[(base >> 2) + lane];
        float4 v1 = row[(base >> 2) + 32 + lane];
        float4 v2 = row[(base >> 2) + 64 + lane];
        float4 v3 = row[(base >> 2) + 96 + lane];
        float c16[16] = {v0.x, v0.y, v0.z, v0.w, v1.x, v1.y, v1.z, v1.w,
                         v2.x, v2.y, v2.z, v2.w, v3.x, v3.y, v3.z, v3.w};
#pragma unroll
        for (int h = 0; h < 4; h++) {
#pragma unroll
            for (int c = 0; c < 4; c++) {
                float f = c16[h * 4 + c];
                unsigned m = __ballot_sync(0xffffffffu, f > 0.0f);
                if (f > 0.0f) {
                    int pos = cnt + __popc(m & ((1u << lane) - 1u));
                    if (pos < MAXDEG)
                        g_cols[warp * MAXDEG + pos] = base + h * 128 + lane * 4 + c;
                }
                cnt += __popc(m);
            }
        }
    }
    if (lane == 0) g_deg[warp] = cnt < MAXDEG ? cnt : MAXDEG;
}

// ===== HMMA GEMM (fp16): wh = x @ W.  M-tile 64 -> 256 CTAs, 2/SM ==========
#define KC 32
#define NCH (DIN_ / KC)          // 16
#define A_STG 8192               // 64 rows * 128B
#define B_STG 8192               // 32 k * 128 n * 2B
#define SM_A 0
#define SM_B (2 * A_STG)
#define SM_SD (SM_B + 2 * B_STG)          // s_sm[64], d_sm[64]
#define SM_AV (SM_SD + 512)               // a_s[128], a_d[128]
#define SM_CS (SM_AV + 1024)              // cs[128]
#define SMEM_TOTAL (SM_CS + 512)

__device__ __forceinline__ uint32_t a_off(int r, int gran) {
    return (uint32_t)(r * 128 + ((gran ^ (r & 7)) << 4));
}
__device__ __forceinline__ uint32_t b_off2(int k, int gran) {
    return (uint32_t)(k * 256 + ((gran ^ (k & 7)) << 4));
}

__global__ __launch_bounds__(256, 2) void gemm_hmma_kernel(
    const float* __restrict__ x, const float* __restrict__ a) {
    extern __shared__ char smem[];
    const uint32_t sb = smem_u32(smem);
    const int tid = threadIdx.x;
    const int wid = tid >> 5, lane = tid & 31;
    const int wm = wid >> 1, wn = wid & 1;     // warp tile: 16 rows x 64 cols
    const int tig = lane & 3, grp = lane >> 2;

    float* s_sm = (float*)(smem + SM_SD);
    float* d_sm = (float*)(smem + SM_SD + 256);
    float* a_s  = (float*)(smem + SM_AV);
    float* a_d  = (float*)(smem + SM_AV + 512);
    float* cs   = (float*)(smem + SM_CS);
    if (tid < 128) {
        cs[tid] = 0.0f;
        a_s[tid] = a[tid]; a_d[tid] = a[DOUT_ + tid];
    }
    if (tid < 64) { s_sm[tid] = 0.0f; d_sm[tid] = 0.0f; }

    const int R0 = blockIdx.x * 64;
    const int arow = tid >> 2, akoff = (tid & 3) * 8;   // 4 threads/row, 8 floats each
    const float* pA = x + (size_t)(R0 + arow) * DIN_ + akoff;
    const int bk = tid >> 3, bgr = (tid & 7) * 2;
    const uint4* Wh4 = (const uint4*)g_Wh;

    float acc[8][4];
#pragma unroll
    for (int j = 0; j < 8; j++)
#pragma unroll
        for (int q = 0; q < 4; q++) acc[j][q] = 0.0f;

    float4 ra[2];
    uint4 rbh[2];
    ra[0] = *(const float4*)(pA);
    ra[1] = *(const float4*)(pA + 4);
    {
        int gi = bk * 16 + bgr;
        rbh[0] = Wh4[gi];  rbh[1] = Wh4[gi + 1];
    }

    for (int c = 0; c < NCH; c++) {
        const int buf = c & 1;
        char* Abuf = smem + SM_A + buf * A_STG;
        char* Bbuf = smem + SM_B + buf * B_STG;

        {
            const float* fa = (const float*)ra;
#pragma unroll
            for (int p = 0; p < 4; p++) {
                uint32_t hv = pack_half(fa[2 * p], fa[2 * p + 1]);
                int kl = akoff + 2 * p;
                int gr = kl >> 3, wi = (kl & 7) * 2;
                *(uint32_t*)(Abuf + a_off(arow, gr) + wi) = hv;
            }
            *(uint4*)(Bbuf + b_off2(bk, bgr))     = rbh[0];
            *(uint4*)(Bbuf + b_off2(bk, bgr + 1)) = rbh[1];
        }
        __syncthreads();

        if (c + 1 < NCH) {
            const float* qA = pA + (c + 1) * KC;
            ra[0] = *(const float4*)(qA);
            ra[1] = *(const float4*)(qA + 4);
            int gi = (c + 1) * 512 + bk * 16 + bgr;
            rbh[0] = Wh4[gi];  rbh[1] = Wh4[gi + 1];
        }

        const uint32_t Abase = sb + SM_A + buf * A_STG;
        const uint32_t Bbase = sb + SM_B + buf * B_STG;
#pragma unroll
        for (int ks = 0; ks < 2; ks++) {
            uint32_t ahi[4];
            {
                int R = wm * 16 + (lane & 15);
                int gh = 2 * ks + (lane >> 4);
                ldm_x4(ahi, Abase + a_off(R, gh));
            }
            int kk = 16 * ks + (lane & 15);
#pragma unroll
            for (int ntp = 0; ntp < 4; ntp++) {
                int gn = wn * 8 + ntp * 2 + (lane >> 4);
                uint32_t bb[4];
                ldm_x4t(bb, Bbase + b_off2(kk, gn));
                mma_f16(acc[ntp * 2],     ahi, bb);
                mma_f16(acc[ntp * 2 + 1], ahi, bb + 2);
            }
        }
        __syncthreads();
    }

    // ---- epilogue: store wh (fp16), fused s/d dots + column sums ----
    float sacc[2] = {0, 0}, dacc[2] = {0, 0};
    int rbase = R0 + wm * 16 + grp;
#pragma unroll
    for (int nt = 0; nt < 8; nt++) {
        int col = wn * 64 + nt * 8 + tig * 2;
        float* cf = acc[nt];
        sacc[0] += cf[0] * a_s[col] + cf[1] * a_s[col + 1];
        sacc[1] += cf[2] * a_s[col] + cf[3] * a_s[col + 1];
        dacc[0] += cf[0] * a_d[col] + cf[1] * a_d[col + 1];
        dacc[1] += cf[2] * a_d[col] + cf[3] * a_d[col + 1];
        *(__half2*)&g_whh[(size_t)rbase * DOUT_ + col] =
            __float22half2_rn(make_float2(cf[0], cf[1]));
        *(__half2*)&g_whh[(size_t)(rbase + 8) * DOUT_ + col] =
            __float22half2_rn(make_float2(cf[2], cf[3]));

        float v0 = cf[0] + cf[2];
        float v1 = cf[1] + cf[3];
#pragma unroll
        for (int off = 16; off >= 4; off >>= 1) {
            v0 += __shfl_down_sync(0xffffffffu, v0, off);
            v1 += __shfl_down_sync(0xffffffffu, v1, off);
        }
        if (lane < 4) {
            atomicAdd(&cs[col], v0);
            atomicAdd(&cs[col + 1], v1);
        }
    }
#pragma unroll
    for (int h = 0; h < 2; h++) {
        sacc[h] += __shfl_xor_sync(0xffffffffu, sacc[h], 1);
        sacc[h] += __shfl_xor_sync(0xffffffffu, sacc[h], 2);
        dacc[h] += __shfl_xor_sync(0xffffffffu, dacc[h], 1);
        dacc[h] += __shfl_xor_sync(0xffffffffu, dacc[h], 2);
    }
    if (tig == 0) {
        int r = wm * 16 + grp;
        atomicAdd(&s_sm[r], sacc[0]);
        atomicAdd(&s_sm[r + 8], sacc[1]);
        atomicAdd(&d_sm[r], dacc[0]);
        atomicAdd(&d_sm[r + 8], dacc[1]);
    }
    __syncthreads();
    if (tid < 64) {
        int b = R0 / N_;
        int il = (R0 % N_) + tid;
        g_sT[il * 4 + b] = s_sm[tid];
        g_dT[il * 4 + b] = d_sm[tid];
    }
    if (tid < 128) {
        int b = R0 / N_;
        atomicAdd(&g_sumwh[b * DOUT_ + tid], cs[tid]);
    }
}

// ==== attention SpMM: warp per (row, graph-pair); register softmax =========
__global__ __launch_bounds__(256) void attn_kernel() {
    __shared__ float sh_e[8][MAXDEG][2];   // fallback only (deg > 32)
    __shared__ int   sh_j[8][MAXDEG];
    int lane = threadIdx.x & 31;
    int w = threadIdx.x >> 5;
    int rl = w >> 1, pr = w & 1;
    int i = blockIdx.x * 4 + rl;
    int deg = g_deg[i];
    int b0 = 2 * pr;

    if (deg == 0) {
        float inv = 1.0f / (float)N_;
#pragma unroll
        for (int q = 0; q < 2; q++) {
            int b = b0 + q;
            float4 m = ((const float4*)&g_sumwh[b * DOUT_])[lane];
            uint2 o;
            o.x = pack_half(m.x * inv, m.y * inv);
            o.y = pack_half(m.z * inv, m.w * inv);
            ((uint2*)&g_outh[((size_t)b * N_ + i) * DOUT_])[lane] = o;
        }
        return;
    }

    const uint2* whA = (const uint2*)g_whh + (size_t)b0 * N_ * 32;
    const uint2* whB = whA + (size_t)N_ * 32;
    float aA0 = 0.f, aA1 = 0.f, aA2 = 0.f, aA3 = 0.f;
    float aB0 = 0.f, aB1 = 0.f, aB2 = 0.f, aB3 = 0.f;
    float2 s2 = *(const float2*)&g_sT[i * 4 + b0];

    if (deg <= 32) {
        // -------- register softmax: lane t owns edge t --------
        int jreg = 0;
        float e0 = NEG_BIG, e1 = NEG_BIG;
        if (lane < deg) {
            jreg = g_cols[i * MAXDEG + lane];
            float2 d2 = *(const float2*)&g_dT[jreg * 4 + b0];
            e0 = s2.x + d2.x; e0 = e0 > 0.f ? e0 : 0.01f * e0;
            e1 = s2.y + d2.y; e1 = e1 > 0.f ? e1 : 0.01f * e1;
        }
        float mx0 = e0, mx1 = e1;
#pragma unroll
        for (int off = 16; off > 0; off >>= 1) {
            mx0 = fmaxf(mx0, __shfl_xor_sync(0xffffffffu, mx0, off));
            mx1 = fmaxf(mx1, __shfl_xor_sync(0xffffffffu, mx1, off));
        }
        float p0 = lane < deg ? __expf(e0 - mx0) : 0.f;
        float p1 = lane < deg ? __expf(e1 - mx1) : 0.f;
        float se0 = p0, se1 = p1;
#pragma unroll
        for (int off = 16; off > 0; off >>= 1) {
            se0 += __shfl_xor_sync(0xffffffffu, se0, off);
            se1 += __shfl_xor_sync(0xffffffffu, se1, off);
        }
        float pA = p0 / se0, pB = p1 / se1;

        int k = 0;
        for (; k + 4 <= deg; k += 4) {
            int   jk[4]; float pAk[4], pBk[4];
#pragma unroll
            for (int u = 0; u < 4; u++) {
                jk[u]  = __shfl_sync(0xffffffffu, jreg, k + u);
                pAk[u] = __shfl_sync(0xffffffffu, pA, k + u);
                pBk[u] = __shfl_sync(0xffffffffu, pB, k + u);
            }
            uint2 vA[4], vB[4];
#pragma unroll
            for (int u = 0; u < 4; u++) {
                size_t o = (size_t)jk[u] * 32 + lane;
                vA[u] = whA[o]; vB[u] = whB[o];
            }
#pragma unroll
            for (int u = 0; u < 4; u++) {
                float2 f;
                f = __half22float2(*(__half2*)&vA[u].x); aA0 += pAk[u] * f.x; aA1 += pAk[u] * f.y;
                f = __half22float2(*(__half2*)&vA[u].y); aA2 += pAk[u] * f.x; aA3 += pAk[u] * f.y;
                f = __half22float2(*(__half2*)&vB[u].x); aB0 += pBk[u] * f.x; aB1 += pBk[u] * f.y;
                f = __half22float2(*(__half2*)&vB[u].y); aB2 += pBk[u] * f.x; aB3 += pBk[u] * f.y;
            }
        }
        for (; k < deg; k++) {
            int   jk  = __shfl_sync(0xffffffffu, jreg, k);
            float pAk = __shfl_sync(0xffffffffu, pA, k);
            float pBk = __shfl_sync(0xffffffffu, pB, k);
            size_t o = (size_t)jk * 32 + lane;
            uint2 vA0 = whA[o], vB0 = whB[o];
            float2 f;
            f = __half22float2(*(__half2*)&vA0.x); aA0 += pAk * f.x; aA1 += pAk * f.y;
            f = __half22float2(*(__half2*)&vA0.y); aA2 += pAk * f.x; aA3 += pAk * f.y;
            f = __half22float2(*(__half2*)&vB0.x); aB0 += pBk * f.x; aB1 += pBk * f.y;
            f = __half22float2(*(__half2*)&vB0.y); aB2 += pBk * f.x; aB3 += pBk * f.y;
        }
    } else {
        // -------- fallback: smem-staged softmax (rare, exact) --------
        float mx0 = NEG_BIG, mx1 = NEG_BIG;
        for (int t = lane; t < deg; t += 32) {
            int j = g_cols[i * MAXDEG + t];
            sh_j[w][t] = j;
            float2 d2 = *(const float2*)&g_dT[j * 4 + b0];
            float e0 = s2.x + d2.x; e0 = e0 > 0.f ? e0 : 0.01f * e0;
            float e1 = s2.y + d2.y; e1 = e1 > 0.f ? e1 : 0.01f * e1;
            *(float2*)sh_e[w][t] = make_float2(e0, e1);
            mx0 = fmaxf(mx0, e0); mx1 = fmaxf(mx1, e1);
        }
#pragma unroll
        for (int off = 16; off > 0; off >>= 1) {
            mx0 = fmaxf(mx0, __shfl_xor_sync(0xffffffffu, mx0, off));
            mx1 = fmaxf(mx1, __shfl_xor_sync(0xffffffffu, mx1, off));
        }
        __syncwarp();
        float se0 = 0.f, se1 = 0.f;
        for (int t = lane; t < deg; t += 32) {
            float2 e = *(float2*)sh_e[w][t];
            float p0 = __expf(e.x - mx0), p1 = __expf(e.y - mx1);
            *(float2*)sh_e[w][t] = make_float2(p0, p1);
            se0 += p0; se1 += p1;
        }
#pragma unroll
        for (int off = 16; off > 0; off >>= 1) {
            se0 += __shfl_xor_sync(0xffffffffu, se0, off);
            se1 += __shfl_xor_sync(0xffffffffu, se1, off);
        }
        float iv0 = 1.f / se0, iv1 = 1.f / se1;
        __syncwarp();
        for (int k = 0; k < deg; k++) {
            size_t o0 = (size_t)sh_j[w][k] * 32 + lane;
            uint2 vA0 = whA[o0], vB0 = whB[o0];
            float2 p0 = *(float2*)sh_e[w][k];
            float pA0 = p0.x * iv0, pB0 = p0.y * iv1;
            float2 f;
            f = __half22float2(*(__half2*)&vA0.x); aA0 += pA0 * f.x; aA1 += pA0 * f.y;
            f = __half22float2(*(__half2*)&vA0.y); aA2 += pA0 * f.x; aA3 += pA0 * f.y;
            f = __half22float2(*(__half2*)&vB0.x); aB0 += pB0 * f.x; aB1 += pB0 * f.y;
            f = __half22float2(*(__half2*)&vB0.y); aB2 += pB0 * f.x; aB3 += pB0 * f.y;
        }
    }

    uint2 oA, oB;
    oA.x = pack_half(aA0, aA1); oA.y = pack_half(aA2, aA3);
    oB.x = pack_half(aB0, aB1); oB.y = pack_half(aB2, aB3);
    ((uint2*)&g_outh[((size_t)b0 * N_ + i) * DOUT_])[lane] = oA;
    ((uint2*)&g_outh[((size_t)(b0 + 1) * N_ + i) * DOUT_])[lane] = oB;
}

// ==== final: y = relu(adj @ out), warp per (row, graph-pair) ================
__global__ __launch_bounds__(256) void final_kernel(float* __restrict__ y) {
    int lane = threadIdx.x & 31;
    int w = threadIdx.x >> 5;
    int rl = w >> 1, pr = w & 1;
    int i = blockIdx.x * 4 + rl;
    int deg = g_deg[i];
    int b0 = 2 * pr;

    const uint2* ouA = (const uint2*)g_outh + (size_t)b0 * N_ * 32;
    const uint2* ouB = ouA + (size_t)N_ * 32;
    float aA0 = 0.f, aA1 = 0.f, aA2 = 0.f, aA3 = 0.f;
    float aB0 = 0.f, aB1 = 0.f, aB2 = 0.f, aB3 = 0.f;

    if (deg <= 32) {
        int jreg = lane < deg ? g_cols[i * MAXDEG + lane] : 0;
        int k = 0;
        for (; k + 4 <= deg; k += 4) {
            int jk[4];
#pragma unroll
            for (int u = 0; u < 4; u++) jk[u] = __shfl_sync(0xffffffffu, jreg, k + u);
            uint2 vA[4], vB[4];
#pragma unroll
            for (int u = 0; u < 4; u++) {
                size_t o = (size_t)jk[u] * 32 + lane;
                vA[u] = ouA[o]; vB[u] = ouB[o];
            }
#pragma unroll
            for (int u = 0; u < 4; u++) {
                float2 f;
                f = __half22float2(*(__half2*)&vA[u].x); aA0 += f.x; aA1 += f.y;
                f = __half22float2(*(__half2*)&vA[u].y); aA2 += f.x; aA3 += f.y;
                f = __half22float2(*(__half2*)&vB[u].x); aB0 += f.x; aB1 += f.y;
                f = __half22float2(*(__half2*)&vB[u].y); aB2 += f.x; aB3 += f.y;
            }
        }
        for (; k < deg; k++) {
            int jk = __shfl_sync(0xffffffffu, jreg, k);
            size_t o0 = (size_t)jk * 32 + lane;
            uint2 vA0 = ouA[o0], vB0 = ouB[o0];
            float2 f;
            f = __half22float2(*(__half2*)&vA0.x); aA0 += f.x; aA1 += f.y;
            f = __half22float2(*(__half2*)&vA0.y); aA2 += f.x; aA3 += f.y;
            f = __half22float2(*(__half2*)&vB0.x); aB0 += f.x; aB1 += f.y;
            f = __half22float2(*(__half2*)&vB0.y); aB2 += f.x; aB3 += f.y;
        }
    } else {
        for (int k = 0; k < deg; k++) {
            size_t o0 = (size_t)g_cols[i * MAXDEG + k] * 32 + lane;
            uint2 vA0 = ouA[o0], vB0 = ouB[o0];
            float2 f;
            f = __half22float2(*(__half2*)&vA0.x); aA0 += f.x; aA1 += f.y;
            f = __half22float2(*(__half2*)&vA0.y); aA2 += f.x; aA3 += f.y;
            f = __half22float2(*(__half2*)&vB0.x); aB0 += f.x; aB1 += f.y;
            f = __half22float2(*(__half2*)&vB0.y); aB2 += f.x; aB3 += f.y;
        }
    }
    float4 rA = make_float4(fmaxf(aA0, 0.f), fmaxf(aA1, 0.f),
                            fmaxf(aA2, 0.f), fmaxf(aA3, 0.f));
    float4 rB = make_float4(fmaxf(aB0, 0.f), fmaxf(aB1, 0.f),
                            fmaxf(aB2, 0.f), fmaxf(aB3, 0.f));
    ((float4*)&y[((size_t)b0 * N_ + i) * DOUT_])[lane] = rA;
    ((float4*)&y[((size_t)(b0 + 1) * N_ + i) * DOUT_])[lane] = rB;
}

// ---------------- launch ----------------
extern "C" void kernel_launch(void* const* d_in, const int* in_sizes, int n_in,
                              void* d_out, int out_size) {
    const float* x   = (const float*)d_in[0];  // (B, N, DIN)
    const float* adj = (const float*)d_in[1];  // (N, N)
    const float* wts = (const float*)d_in[2];  // (DIN, DOUT)
    const float* a   = (const float*)d_in[3];  // (2*DOUT, 1)
    float* y = (float*)d_out;

    static cudaStream_t s2;
    static cudaEvent_t evA, evC;
    static int inited = 0;
    if (!inited) {
        cudaFuncSetAttribute(gemm_hmma_kernel,
                             cudaFuncAttributeMaxDynamicSharedMemorySize, SMEM_TOTAL);
        cudaStreamCreateWithFlags(&s2, cudaStreamNonBlocking);
        cudaEventCreateWithFlags(&evA, cudaEventDisableTiming);
        cudaEventCreateWithFlags(&evC, cudaEventDisableTiming);
        inited = 1;
    }
    cudaStream_t s0 = 0;

    // fork: csr on s2 overlaps convW+GEMM on s0; join before attn
    cudaEventRecord(evA, s0);
    cudaStreamWaitEvent(s2, evA, 0);
    csr_build_kernel<<<N_ / 8, 256, 0, s2>>>(adj);
    cudaEventRecord(evC, s2);

    convw_kernel<<<DIN_ * DOUT_ / 1024, 256, 0, s0>>>(wts);
    gemm_hmma_kernel<<<(B_ * N_) / 64, 256, SMEM_TOTAL, s0>>>(x, a);
    cudaStreamWaitEvent(s0, evC, 0);

    attn_kernel<<<N_ / 4, 256, 0, s0>>>();
    final_kernel<<<N_ / 4, 256, 0, s0>>>(y);
}